// round 15
// baseline (speedup 1.0000x reference)
#include <cuda_runtime.h>
#include <cuda_bf16.h>
#include <stdint.h>

// ---------------- problem constants ----------------
#define NFREQ  33
#define FC     66
#define FCP    80
#define BATCH  8
#define CIN    64
#define COUT   64
#define TLEN   16384
#define NFRAME 513
#define NFS    576
#define MS     (BATCH*NFS)   // 4608

// ---------------- global scratch (16B-aligned: cp.async sources) -------------
__device__ __align__(256) __nv_bfloat16 g_Uh[(size_t)FC * CIN  * MS];
__device__ __align__(256) __nv_bfloat16 g_Ul[(size_t)FC * CIN  * MS];
__device__ __align__(256) __nv_bfloat16 g_Yh[(size_t)FC * COUT * MS];
__device__ __align__(256) __nv_bfloat16 g_Yl[(size_t)FC * COUT * MS];
__device__ __align__(256) __nv_bfloat16 g_Wh[(size_t)NFREQ * COUT * CIN];
__device__ __align__(256) __nv_bfloat16 g_Wl[(size_t)NFREQ * COUT * CIN];
__device__ __align__(256) __nv_bfloat16 g_Bth[FCP * 72], g_Btl[FCP * 72];  // [fc][t], pitch 144B
__device__ __align__(256) __nv_bfloat16 g_IDh[64 * 88],  g_IDl[64 * 88];   // [t'][fc], pitch 176B

__device__ __forceinline__ void mma_bf16(float* d, const uint32_t* a, const uint32_t* b) {
    asm volatile(
        "mma.sync.aligned.m16n8k16.row.col.f32.bf16.bf16.f32 "
        "{%0,%1,%2,%3}, {%4,%5,%6,%7}, {%8,%9}, {%0,%1,%2,%3};"
        : "+f"(d[0]), "+f"(d[1]), "+f"(d[2]), "+f"(d[3])
        : "r"(a[0]), "r"(a[1]), "r"(a[2]), "r"(a[3]), "r"(b[0]), "r"(b[1]));
}
__device__ __forceinline__ void ldsm4(uint32_t* r, uint32_t a) {
    asm volatile("ldmatrix.sync.aligned.m8n8.x4.shared.b16 {%0,%1,%2,%3}, [%4];"
        : "=r"(r[0]), "=r"(r[1]), "=r"(r[2]), "=r"(r[3]) : "r"(a));
}
__device__ __forceinline__ void ldsm4t(uint32_t* r, uint32_t a) {
    asm volatile("ldmatrix.sync.aligned.m8n8.x4.trans.shared.b16 {%0,%1,%2,%3}, [%4];"
        : "=r"(r[0]), "=r"(r[1]), "=r"(r[2]), "=r"(r[3]) : "r"(a));
}
__device__ __forceinline__ void ldsm2(uint32_t* r, uint32_t a) {
    asm volatile("ldmatrix.sync.aligned.m8n8.x2.shared.b16 {%0,%1}, [%2];"
        : "=r"(r[0]), "=r"(r[1]) : "r"(a));
}
__device__ __forceinline__ void cpa16(uint32_t smem_dst, const void* gsrc) {
    asm volatile("cp.async.ca.shared.global [%0], [%1], 16;"
        :: "r"(smem_dst), "l"(gsrc));
}
__device__ __forceinline__ void cpa_wait() {
    asm volatile("cp.async.commit_group;\n\tcp.async.wait_group 0;" ::: "memory");
}
__device__ __forceinline__ void split2(float v, uint16_t& h, uint16_t& l) {
    __nv_bfloat16 hb = __float2bfloat16(v);
    __nv_bfloat16 lb = __float2bfloat16(v - __bfloat162float(hb));
    h = *(uint16_t*)&hb; l = *(uint16_t*)&lb;
}

// =====================================================================
// fused table + weight precompute (one launch)
// =====================================================================
__global__ __launch_bounds__(256) void k_prep_all(const float* __restrict__ weight) {
    if (blockIdx.x < 528) {
        int gid = blockIdx.x * 256 + threadIdx.x;
        if (gid >= NFREQ * COUT * CIN) return;
        int f = gid / (COUT * CIN);
        int rem = gid - f * (COUT * CIN);
        int o = rem >> 6, i = rem & 63;
        float w = weight[((size_t)o * CIN + i) * NFREQ + f];
        uint16_t h, l; split2(w, h, l);
        size_t dst = ((size_t)f * COUT + o) * CIN + i;
        ((uint16_t*)g_Wh)[dst] = h; ((uint16_t*)g_Wl)[dst] = l;
        return;
    }
    int tid0 = (blockIdx.x - 528) * 256 + threadIdx.x;
    for (int idx = tid0; idx < FCP * 72; idx += 32 * 256) {
        int fc = idx / 72, t = idx - fc * 72;
        float v = 0.f;
        if (fc < FC && t < 64) {
            int f = fc >> 1;
            float s, c;
            sincospif((float)(f * t) / 32.0f, &s, &c);
            v = (fc & 1) ? -s : c;
            v *= 0.5f - 0.5f * cospif((float)t / 32.0f);
        }
        uint16_t h, l; split2(v, h, l);
        ((uint16_t*)g_Bth)[idx] = h; ((uint16_t*)g_Btl)[idx] = l;
    }
    for (int idx = tid0; idx < 64 * 88; idx += 32 * 256) {
        int t = idx / 88, fc = idx - t * 88;
        float v = 0.f;
        if (fc < FC) {
            int f = fc >> 1;
            float s, c;
            sincospif((float)(f * t) / 32.0f, &s, &c);
            float af = (f == 0 || f == 32) ? 1.0f : 2.0f;
            if (fc & 1) v = (f == 0 || f == 32) ? 0.f : -s * af;
            else        v = c * af;
            v *= (0.5f - 0.5f * cospif((float)t / 32.0f)) * (1.0f / 64.0f);
        }
        uint16_t h, l; split2(v, h, l);
        ((uint16_t*)g_IDh)[idx] = h; ((uint16_t*)g_IDl)[idx] = l;
    }
}

// =====================================================================
// Stage 1: STFT (R14, unchanged).
// smem: AH@0(10560) AL@10560 BH@21120(11520) BL@32640; tot 44160
// =====================================================================
#define STFT_SMEM 44160
#define CHB 5280
__global__ __launch_bounds__(256, 2) void k_stft(const float* __restrict__ x) {
    extern __shared__ __align__(16) char SM[];
    const uint32_t smb = (uint32_t)__cvta_generic_to_shared(SM);
    const int tid = threadIdx.x, w = tid >> 5, lane = tid & 31;
    const int g = lane >> 2, tig = lane & 3;
    const int mat = lane >> 3, row = lane & 7, matb = mat & 1;
    const int nch = blockIdx.x, i0 = blockIdx.y * 2, b = blockIdx.z;

    for (int idx = tid; idx < 720; idx += 256) {
        cpa16(smb + 21120 + idx * 16, (const char*)g_Bth + idx * 16);
        cpa16(smb + 32640 + idx * 16, (const char*)g_Btl + idx * 16);
    }

    const float* xr = x + ((size_t)(b * CIN + i0)) * TLEN;
    for (int idx = tid; idx < 4224; idx += 256) {
        int il = idx >= 2112;
        int s = idx - il * 2112;
        int src = nch * 2048 + s - 32;
        src = src < 0 ? -src : src;
        src = src >= TLEN ? 2 * TLEN - 2 - src : src;
        float v = xr[(size_t)il * TLEN + src];
        uint16_t h, l; split2(v, h, l);
        int off = il * CHB + (s >> 5) * 80 + (s & 31) * 2;
        *(uint16_t*)(SM + off) = h;
        *(uint16_t*)(SM + 10560 + off) = l;
    }
    cpa_wait();
    __syncthreads();

    const int mb = (w & 3) * 32, nb = (w >> 2) * 40;
    const int il = mb >> 6;
    const int f_loc = (mb & 63) + (mat & 1) * 8 + row;
    const int t0l = (mat >> 1) * 8;
    uint32_t aK[4];
#pragma unroll
    for (int kc = 0; kc < 4; kc++) {
        int tt = t0l + kc * 16;
        aK[kc] = smb + (uint32_t)(il * CHB + (f_loc + (tt >> 5)) * 80 + (tt & 31) * 2);
    }
    const uint32_t bB = smb + 21120u + (uint32_t)((nb + row) * 144 + matb * 16);

    float d[2][5][4];
#pragma unroll
    for (int r = 0; r < 2; r++)
#pragma unroll
        for (int nt = 0; nt < 5; nt++)
#pragma unroll
            for (int q = 0; q < 4; q++) d[r][nt][q] = 0.f;

#pragma unroll
    for (int kc = 0; kc < 4; kc++) {
        uint32_t bh[5][2], bl[5][2];
#pragma unroll
        for (int nt = 0; nt < 5; nt++) {
            ldsm2(bh[nt], bB + nt * 1152 + kc * 32);
            ldsm2(bl[nt], bB + 11520 + nt * 1152 + kc * 32);
        }
#pragma unroll
        for (int r = 0; r < 2; r++) {
            uint32_t ah[4], al[4];
            ldsm4(ah, aK[kc] + r * 1280);
            ldsm4(al, aK[kc] + 10560 + r * 1280);
#pragma unroll
            for (int nt = 0; nt < 5; nt++) {
                mma_bf16(d[r][nt], ah, bh[nt]);
                mma_bf16(d[r][nt], al, bh[nt]);
                mma_bf16(d[r][nt], ah, bl[nt]);
            }
        }
    }
    __syncthreads();

#pragma unroll
    for (int r = 0; r < 2; r++)
#pragma unroll
        for (int nt = 0; nt < 5; nt++) {
            int m = mb + r * 16 + g;
            int n = nb + nt * 8 + tig * 2;
            uint16_t h, l;
            if (n < FC) {
                split2(d[r][nt][0], h, l);
                *(uint16_t*)(SM + n * 264 + m * 2) = h;
                *(uint16_t*)(SM + 17472 + n * 264 + m * 2) = l;
                split2(d[r][nt][2], h, l);
                *(uint16_t*)(SM + n * 264 + (m + 8) * 2) = h;
                *(uint16_t*)(SM + 17472 + n * 264 + (m + 8) * 2) = l;
            }
            if (n + 1 < FC) {
                split2(d[r][nt][1], h, l);
                *(uint16_t*)(SM + (n + 1) * 264 + m * 2) = h;
                *(uint16_t*)(SM + 17472 + (n + 1) * 264 + m * 2) = l;
                split2(d[r][nt][3], h, l);
                *(uint16_t*)(SM + (n + 1) * 264 + (m + 8) * 2) = h;
                *(uint16_t*)(SM + 17472 + (n + 1) * 264 + (m + 8) * 2) = l;
            }
        }
    __syncthreads();

    uint32_t* uh = (uint32_t*)g_Uh;
    uint32_t* ul = (uint32_t*)g_Ul;
    const size_t cb = (size_t)b * NFS + nch * 64;
    for (int idx = tid; idx < 4224; idx += 256) {
        int rw = idx >> 5, wq = idx & 31;
        int fc = rw >> 1, il2 = rw & 1;
        uint32_t vh = *(uint32_t*)(SM + fc * 264 + il2 * 128 + wq * 4);
        uint32_t vl = *(uint32_t*)(SM + 17472 + fc * 264 + il2 * 128 + wq * 4);
        size_t di = ((((size_t)fc * CIN + i0 + il2) * MS) + cb) >> 1;
        uh[di + wq] = vh;
        ul[di + wq] = vl;
    }
}

// =====================================================================
// Stage 2: mix (R14, unchanged).
// smem: AH@0(33792) AL@33792 BH@67584(9216) BL@76800; tot 86016
// =====================================================================
#define MIX_SMEM 86016
__global__ __launch_bounds__(256, 2) void k_mix() {
    extern __shared__ __align__(16) char SM[];
    const uint32_t smb = (uint32_t)__cvta_generic_to_shared(SM);
    const int tid = threadIdx.x, w = tid >> 5, lane = tid & 31;
    const int g = lane >> 2, tig = lane & 3;
    const int mat = lane >> 3, row = lane & 7, matb = mat & 1;
    const int fc = blockIdx.y, f = fc >> 1;
    const size_t c0 = (size_t)blockIdx.x * 256;

    {
        const char* uhp = (const char*)g_Uh;
        const char* ulp = (const char*)g_Ul;
        for (int idx = tid; idx < 2048; idx += 256) {
            int i = idx >> 5, ch = idx & 31;
            size_t so = ((((size_t)fc * CIN + i) * MS) + c0) * 2 + ch * 16;
            cpa16(smb + i * 528 + ch * 16, uhp + so);
            cpa16(smb + 33792 + i * 528 + ch * 16, ulp + so);
        }
    }
    {
        const char* whp = (const char*)g_Wh;
        const char* wlp = (const char*)g_Wl;
        for (int idx = tid; idx < 512; idx += 256) {
            int o = idx >> 3, ch = idx & 7;
            size_t so = (((size_t)f * COUT + o) * CIN) * 2 + ch * 16;
            cpa16(smb + 67584 + o * 144 + ch * 16, whp + so);
            cpa16(smb + 76800 + o * 144 + ch * 16, wlp + so);
        }
    }
    cpa_wait();
    __syncthreads();

    const int mb = (w & 3) * 64, nb = (w >> 2) * 32;
    const int krp = (mat >> 1) * 8 + row;
    const uint32_t aB = smb + (uint32_t)(krp * 528);
    const uint32_t bB = smb + 67584u + (uint32_t)((nb + row) * 144 + matb * 16);
    int mcol[4];
#pragma unroll
    for (int mt = 0; mt < 4; mt++) mcol[mt] = (mb + mt * 16 + (mat & 1) * 8) * 2;

    float d[4][4][4];
#pragma unroll
    for (int mt = 0; mt < 4; mt++)
#pragma unroll
        for (int nt = 0; nt < 4; nt++)
#pragma unroll
            for (int q = 0; q < 4; q++) d[mt][nt][q] = 0.f;

#pragma unroll
    for (int kc = 0; kc < 4; kc++) {
        uint32_t bh[4][2], bl[4][2];
#pragma unroll
        for (int nt = 0; nt < 4; nt++) {
            ldsm2(bh[nt], bB + nt * 1152 + kc * 32);
            ldsm2(bl[nt], bB + 9216 + nt * 1152 + kc * 32);
        }
#pragma unroll
        for (int mt = 0; mt < 4; mt++) {
            uint32_t ah[4], al[4];
            ldsm4t(ah, aB + kc * 8448 + mcol[mt]);
            ldsm4t(al, aB + 33792 + kc * 8448 + mcol[mt]);
#pragma unroll
            for (int nt = 0; nt < 4; nt++) {
                mma_bf16(d[mt][nt], ah, bh[nt]);
                mma_bf16(d[mt][nt], al, bh[nt]);
                mma_bf16(d[mt][nt], ah, bl[nt]);
            }
        }
    }
    __syncthreads();   // A dead -> Dt [o][m] pitch 528

#pragma unroll
    for (int mt = 0; mt < 4; mt++)
#pragma unroll
        for (int nt = 0; nt < 4; nt++) {
            int m = mb + mt * 16 + g;
            int oo = nb + nt * 8 + tig * 2;
            uint16_t h, l;
            split2(d[mt][nt][0], h, l);
            *(uint16_t*)(SM + oo * 528 + m * 2) = h;
            *(uint16_t*)(SM + 33792 + oo * 528 + m * 2) = l;
            split2(d[mt][nt][1], h, l);
            *(uint16_t*)(SM + (oo + 1) * 528 + m * 2) = h;
            *(uint16_t*)(SM + 33792 + (oo + 1) * 528 + m * 2) = l;
            split2(d[mt][nt][2], h, l);
            *(uint16_t*)(SM + oo * 528 + (m + 8) * 2) = h;
            *(uint16_t*)(SM + 33792 + oo * 528 + (m + 8) * 2) = l;
            split2(d[mt][nt][3], h, l);
            *(uint16_t*)(SM + (oo + 1) * 528 + (m + 8) * 2) = h;
            *(uint16_t*)(SM + 33792 + (oo + 1) * 528 + (m + 8) * 2) = l;
        }
    __syncthreads();

    uint32_t* yh = (uint32_t*)g_Yh;
    uint32_t* yl = (uint32_t*)g_Yl;
    for (int idx = tid; idx < 8192; idx += 256) {
        int o = idx >> 7, q = idx & 127;
        size_t di = ((((size_t)fc * COUT + o) * MS) + c0) / 2 + q;
        yh[di] = *(uint32_t*)(SM + o * 528 + q * 4);
        yl[di] = *(uint32_t*)(SM + 33792 + o * 528 + q * 4);
    }
}

// =====================================================================
// Stage 3+4: ISTFT frames + OLA.  M=256 tile.
// A: Ys[fc(80)][c(256)] pitch 528; B: ID[t'][fc] pitch 176.
// smem: AH@0(42240) AL@42240 IDH@84480(11264) IDL@95744; tot 107008
// F (fp32, 257x68 = 69904 B) aliases A.
// =====================================================================
#define FRAMES_SMEM 107008
__global__ __launch_bounds__(256) void k_frames_ola(float* __restrict__ out) {
    extern __shared__ __align__(16) char SM[];
    __shared__ float yc[FC];
    __shared__ float inv[32];
    const uint32_t smb = (uint32_t)__cvta_generic_to_shared(SM);
    const int tid = threadIdx.x, w = tid >> 5, lane = tid & 31;
    const int g = lane >> 2, tig = lane & 3;
    const int mat = lane >> 3, row = lane & 7, matb = mat & 1;
    const int o = blockIdx.y;
    const size_t c0 = (size_t)blockIdx.x * 256;

    // A rows via cp.async: 66 rows x 32 chunks of 16B (512B data, pitch 528)
    {
        const char* yhp = (const char*)g_Yh;
        const char* ylp = (const char*)g_Yl;
        for (int idx = tid; idx < 2112; idx += 256) {
            int fc = idx >> 5, ch = idx & 31;
            size_t so = ((((size_t)fc * COUT + o) * MS) + c0) * 2 + ch * 16;
            cpa16(smb + fc * 528 + ch * 16, yhp + so);
            cpa16(smb + 42240 + fc * 528 + ch * 16, ylp + so);
        }
    }
    // ID tables via cp.async
    for (int idx = tid; idx < 704; idx += 256) {
        cpa16(smb + 84480 + idx * 16, (const char*)g_IDh + idx * 16);
        cpa16(smb + 95744 + idx * 16, (const char*)g_IDl + idx * 16);
    }
    // zero-fill K rows 66..79 (float4 stores)
    for (int idx = tid; idx < 448; idx += 256) {
        int r = 66 + (idx >> 5), ch = idx & 31;
        float4 z = make_float4(0.f, 0.f, 0.f, 0.f);
        *(float4*)(SM + r * 528 + ch * 16) = z;
        *(float4*)(SM + 42240 + r * 528 + ch * 16) = z;
    }
    if (tid < FC) {
        float v = 0.f;
        if (blockIdx.x > 0) {
            size_t ei = ((size_t)tid * COUT + o) * MS + c0 - 1;
            v = __bfloat162float(g_Yh[ei]) + __bfloat162float(g_Yl[ei]);
        }
        yc[tid] = v;
    }
    if (tid < 32) {
        float c = cospif((float)tid / 32.0f);
        float w1 = 0.5f - 0.5f * c, w2 = 0.5f + 0.5f * c;
        inv[tid] = 1.0f / (w1 * w1 + w2 * w2);
    }
    cpa_wait();
    __syncthreads();

    const int mb = (w & 3) * 64, nb = (w >> 2) * 32;
    const int krp = (mat >> 1) * 8 + row;
    const uint32_t aB = smb + (uint32_t)(krp * 528);
    const uint32_t bB = smb + 84480u + (uint32_t)((nb + row) * 176 + matb * 16);
    int mcol[4];
#pragma unroll
    for (int mt = 0; mt < 4; mt++) mcol[mt] = (mb + mt * 16 + (mat & 1) * 8) * 2;

    float d[4][4][4];
#pragma unroll
    for (int mt = 0; mt < 4; mt++)
#pragma unroll
        for (int nt = 0; nt < 4; nt++)
#pragma unroll
            for (int q = 0; q < 4; q++) d[mt][nt][q] = 0.f;

#pragma unroll
    for (int kc = 0; kc < 5; kc++) {
        uint32_t bh[4][2], bl[4][2];
#pragma unroll
        for (int nt = 0; nt < 4; nt++) {
            ldsm2(bh[nt], bB + nt * 1408 + kc * 32);
            ldsm2(bl[nt], bB + 11264 + nt * 1408 + kc * 32);
        }
#pragma unroll
        for (int mt = 0; mt < 4; mt++) {
            uint32_t ah[4], al[4];
            ldsm4t(ah, aB + kc * 8448 + mcol[mt]);
            ldsm4t(al, aB + 42240 + kc * 8448 + mcol[mt]);
#pragma unroll
            for (int nt = 0; nt < 4; nt++) {
                mma_bf16(d[mt][nt], ah, bh[nt]);
                mma_bf16(d[mt][nt], al, bh[nt]);
                mma_bf16(d[mt][nt], ah, bl[nt]);
            }
        }
    }

    // boundary frame (c0-1): taps 32..63
    float fm = 0.f;
    if (tid < 32) {
        int t = 32 + tid;
#pragma unroll 11
        for (int q = 0; q < FC; q++) {
            float idv = __bfloat162float(*(__nv_bfloat16*)(SM + 84480 + t * 176 + q * 2))
                      + __bfloat162float(*(__nv_bfloat16*)(SM + 95744 + t * 176 + q * 2));
            fm += idv * yc[q];
        }
    }
    __syncthreads();   // A dead -> F

    float* F = (float*)SM;   // F[i][t'] rows of 68; F[0] = frame c0-1
#pragma unroll
    for (int mt = 0; mt < 4; mt++)
#pragma unroll
        for (int nt = 0; nt < 4; nt++) {
            int m = mb + mt * 16 + g;
            int t = nb + nt * 8 + tig * 2;
            *(float2*)&F[(1 + m) * 68 + t] = make_float2(d[mt][nt][0], d[mt][nt][1]);
            *(float2*)&F[(9 + m) * 68 + t] = make_float2(d[mt][nt][2], d[mt][nt][3]);
        }
    if (tid < 32) F[32 + tid] = fm;
    __syncthreads();

    // OLA: division-free (single wrap possible since r0+255 < 2*NFS)
    const int b0 = (int)(c0 / NFS);
    const int r0 = (int)(c0 - (size_t)b0 * NFS);
    for (int sidx = tid; sidx < 8192; sidx += 256) {
        int i = sidx >> 5, r = sidx & 31;
        int n = r0 + i, b = b0;
        if (n >= NFS) { n -= NFS; b++; }
        if (n < 1 || n >= NFRAME) continue;
        float v = (F[(i + 1) * 68 + r] + F[i * 68 + r + 32]) * inv[r];
        out[(((size_t)(b * COUT + o)) << 14) + (size_t)(n - 1) * 32 + r] = v;
    }
}

// =====================================================================
extern "C" void kernel_launch(void* const* d_in, const int* in_sizes, int n_in,
                              void* d_out, int out_size) {
    const float* x      = (const float*)d_in[0];
    const float* weight = (const float*)d_in[1];
    float* out          = (float*)d_out;
    (void)in_sizes; (void)n_in; (void)out_size;

    static int init = 0;
    if (!init) {
        cudaFuncSetAttribute(k_stft, cudaFuncAttributeMaxDynamicSharedMemorySize, STFT_SMEM);
        cudaFuncSetAttribute(k_mix, cudaFuncAttributeMaxDynamicSharedMemorySize, MIX_SMEM);
        cudaFuncSetAttribute(k_frames_ola, cudaFuncAttributeMaxDynamicSharedMemorySize, FRAMES_SMEM);
        init = 1;
    }

    k_prep_all<<<560, 256>>>(weight);
    k_stft <<<dim3(9, 32, 8), 256, STFT_SMEM>>>(x);
    k_mix  <<<dim3(MS / 256, FC), 256, MIX_SMEM>>>();
    k_frames_ola<<<dim3(MS / 256, COUT), 256, FRAMES_SMEM>>>(out);
}

// round 16
// speedup vs baseline: 1.0600x; 1.0600x over previous
#include <cuda_runtime.h>
#include <cuda_bf16.h>
#include <stdint.h>

// ---------------- problem constants ----------------
#define NFREQ  33
#define FC     66
#define FCP    80
#define BATCH  8
#define CIN    64
#define COUT   64
#define TLEN   16384
#define NFRAME 513
#define NFS    576
#define MS     (BATCH*NFS)   // 4608

// ---------------- global scratch (16B-aligned: cp.async sources) -------------
__device__ __align__(256) __nv_bfloat16 g_Uh[(size_t)FC * CIN  * MS];
__device__ __align__(256) __nv_bfloat16 g_Ul[(size_t)FC * CIN  * MS];
__device__ __align__(256) __nv_bfloat16 g_Yh[(size_t)FC * COUT * MS];
__device__ __align__(256) __nv_bfloat16 g_Yl[(size_t)FC * COUT * MS];
__device__ __align__(256) __nv_bfloat16 g_Wh[(size_t)NFREQ * COUT * CIN];
__device__ __align__(256) __nv_bfloat16 g_Wl[(size_t)NFREQ * COUT * CIN];
__device__ __align__(256) __nv_bfloat16 g_Bth[FCP * 72], g_Btl[FCP * 72];  // [fc][t], pitch 144B
__device__ __align__(256) __nv_bfloat16 g_IDh[64 * 88],  g_IDl[64 * 88];   // [t'][fc], pitch 176B

__device__ __forceinline__ void mma_bf16(float* d, const uint32_t* a, const uint32_t* b) {
    asm volatile(
        "mma.sync.aligned.m16n8k16.row.col.f32.bf16.bf16.f32 "
        "{%0,%1,%2,%3}, {%4,%5,%6,%7}, {%8,%9}, {%0,%1,%2,%3};"
        : "+f"(d[0]), "+f"(d[1]), "+f"(d[2]), "+f"(d[3])
        : "r"(a[0]), "r"(a[1]), "r"(a[2]), "r"(a[3]), "r"(b[0]), "r"(b[1]));
}
__device__ __forceinline__ void ldsm4(uint32_t* r, uint32_t a) {
    asm volatile("ldmatrix.sync.aligned.m8n8.x4.shared.b16 {%0,%1,%2,%3}, [%4];"
        : "=r"(r[0]), "=r"(r[1]), "=r"(r[2]), "=r"(r[3]) : "r"(a));
}
__device__ __forceinline__ void ldsm4t(uint32_t* r, uint32_t a) {
    asm volatile("ldmatrix.sync.aligned.m8n8.x4.trans.shared.b16 {%0,%1,%2,%3}, [%4];"
        : "=r"(r[0]), "=r"(r[1]), "=r"(r[2]), "=r"(r[3]) : "r"(a));
}
__device__ __forceinline__ void ldsm2(uint32_t* r, uint32_t a) {
    asm volatile("ldmatrix.sync.aligned.m8n8.x2.shared.b16 {%0,%1}, [%2];"
        : "=r"(r[0]), "=r"(r[1]) : "r"(a));
}
__device__ __forceinline__ void cpa16(uint32_t smem_dst, const void* gsrc) {
    asm volatile("cp.async.ca.shared.global [%0], [%1], 16;"
        :: "r"(smem_dst), "l"(gsrc));
}
__device__ __forceinline__ void cpa_wait() {
    asm volatile("cp.async.commit_group;\n\tcp.async.wait_group 0;" ::: "memory");
}
__device__ __forceinline__ void split2(float v, uint16_t& h, uint16_t& l) {
    __nv_bfloat16 hb = __float2bfloat16(v);
    __nv_bfloat16 lb = __float2bfloat16(v - __bfloat162float(hb));
    h = *(uint16_t*)&hb; l = *(uint16_t*)&lb;
}

// =====================================================================
// fused table + weight precompute (one launch)
// =====================================================================
__global__ __launch_bounds__(256) void k_prep_all(const float* __restrict__ weight) {
    if (blockIdx.x < 528) {
        int gid = blockIdx.x * 256 + threadIdx.x;
        if (gid >= NFREQ * COUT * CIN) return;
        int f = gid / (COUT * CIN);
        int rem = gid - f * (COUT * CIN);
        int o = rem >> 6, i = rem & 63;
        float w = weight[((size_t)o * CIN + i) * NFREQ + f];
        uint16_t h, l; split2(w, h, l);
        size_t dst = ((size_t)f * COUT + o) * CIN + i;
        ((uint16_t*)g_Wh)[dst] = h; ((uint16_t*)g_Wl)[dst] = l;
        return;
    }
    int tid0 = (blockIdx.x - 528) * 256 + threadIdx.x;
    for (int idx = tid0; idx < FCP * 72; idx += 32 * 256) {
        int fc = idx / 72, t = idx - fc * 72;
        float v = 0.f;
        if (fc < FC && t < 64) {
            int f = fc >> 1;
            float s, c;
            sincospif((float)(f * t) / 32.0f, &s, &c);
            v = (fc & 1) ? -s : c;
            v *= 0.5f - 0.5f * cospif((float)t / 32.0f);
        }
        uint16_t h, l; split2(v, h, l);
        ((uint16_t*)g_Bth)[idx] = h; ((uint16_t*)g_Btl)[idx] = l;
    }
    for (int idx = tid0; idx < 64 * 88; idx += 32 * 256) {
        int t = idx / 88, fc = idx - t * 88;
        float v = 0.f;
        if (fc < FC) {
            int f = fc >> 1;
            float s, c;
            sincospif((float)(f * t) / 32.0f, &s, &c);
            float af = (f == 0 || f == 32) ? 1.0f : 2.0f;
            if (fc & 1) v = (f == 0 || f == 32) ? 0.f : -s * af;
            else        v = c * af;
            v *= (0.5f - 0.5f * cospif((float)t / 32.0f)) * (1.0f / 64.0f);
        }
        uint16_t h, l; split2(v, h, l);
        ((uint16_t*)g_IDh)[idx] = h; ((uint16_t*)g_IDl)[idx] = l;
    }
}

// =====================================================================
// Stage 1: STFT (R14, unchanged).
// smem: AH@0(10560) AL@10560 BH@21120(11520) BL@32640; tot 44160
// =====================================================================
#define STFT_SMEM 44160
#define CHB 5280
__global__ __launch_bounds__(256, 2) void k_stft(const float* __restrict__ x) {
    extern __shared__ __align__(16) char SM[];
    const uint32_t smb = (uint32_t)__cvta_generic_to_shared(SM);
    const int tid = threadIdx.x, w = tid >> 5, lane = tid & 31;
    const int g = lane >> 2, tig = lane & 3;
    const int mat = lane >> 3, row = lane & 7, matb = mat & 1;
    const int nch = blockIdx.x, i0 = blockIdx.y * 2, b = blockIdx.z;

    for (int idx = tid; idx < 720; idx += 256) {
        cpa16(smb + 21120 + idx * 16, (const char*)g_Bth + idx * 16);
        cpa16(smb + 32640 + idx * 16, (const char*)g_Btl + idx * 16);
    }

    const float* xr = x + ((size_t)(b * CIN + i0)) * TLEN;
    for (int idx = tid; idx < 4224; idx += 256) {
        int il = idx >= 2112;
        int s = idx - il * 2112;
        int src = nch * 2048 + s - 32;
        src = src < 0 ? -src : src;
        src = src >= TLEN ? 2 * TLEN - 2 - src : src;
        float v = xr[(size_t)il * TLEN + src];
        uint16_t h, l; split2(v, h, l);
        int off = il * CHB + (s >> 5) * 80 + (s & 31) * 2;
        *(uint16_t*)(SM + off) = h;
        *(uint16_t*)(SM + 10560 + off) = l;
    }
    cpa_wait();
    __syncthreads();

    const int mb = (w & 3) * 32, nb = (w >> 2) * 40;
    const int il = mb >> 6;
    const int f_loc = (mb & 63) + (mat & 1) * 8 + row;
    const int t0l = (mat >> 1) * 8;
    uint32_t aK[4];
#pragma unroll
    for (int kc = 0; kc < 4; kc++) {
        int tt = t0l + kc * 16;
        aK[kc] = smb + (uint32_t)(il * CHB + (f_loc + (tt >> 5)) * 80 + (tt & 31) * 2);
    }
    const uint32_t bB = smb + 21120u + (uint32_t)((nb + row) * 144 + matb * 16);

    float d[2][5][4];
#pragma unroll
    for (int r = 0; r < 2; r++)
#pragma unroll
        for (int nt = 0; nt < 5; nt++)
#pragma unroll
            for (int q = 0; q < 4; q++) d[r][nt][q] = 0.f;

#pragma unroll
    for (int kc = 0; kc < 4; kc++) {
        uint32_t bh[5][2], bl[5][2];
#pragma unroll
        for (int nt = 0; nt < 5; nt++) {
            ldsm2(bh[nt], bB + nt * 1152 + kc * 32);
            ldsm2(bl[nt], bB + 11520 + nt * 1152 + kc * 32);
        }
#pragma unroll
        for (int r = 0; r < 2; r++) {
            uint32_t ah[4], al[4];
            ldsm4(ah, aK[kc] + r * 1280);
            ldsm4(al, aK[kc] + 10560 + r * 1280);
#pragma unroll
            for (int nt = 0; nt < 5; nt++) {
                mma_bf16(d[r][nt], ah, bh[nt]);
                mma_bf16(d[r][nt], al, bh[nt]);
                mma_bf16(d[r][nt], ah, bl[nt]);
            }
        }
    }
    __syncthreads();

#pragma unroll
    for (int r = 0; r < 2; r++)
#pragma unroll
        for (int nt = 0; nt < 5; nt++) {
            int m = mb + r * 16 + g;
            int n = nb + nt * 8 + tig * 2;
            uint16_t h, l;
            if (n < FC) {
                split2(d[r][nt][0], h, l);
                *(uint16_t*)(SM + n * 264 + m * 2) = h;
                *(uint16_t*)(SM + 17472 + n * 264 + m * 2) = l;
                split2(d[r][nt][2], h, l);
                *(uint16_t*)(SM + n * 264 + (m + 8) * 2) = h;
                *(uint16_t*)(SM + 17472 + n * 264 + (m + 8) * 2) = l;
            }
            if (n + 1 < FC) {
                split2(d[r][nt][1], h, l);
                *(uint16_t*)(SM + (n + 1) * 264 + m * 2) = h;
                *(uint16_t*)(SM + 17472 + (n + 1) * 264 + m * 2) = l;
                split2(d[r][nt][3], h, l);
                *(uint16_t*)(SM + (n + 1) * 264 + (m + 8) * 2) = h;
                *(uint16_t*)(SM + 17472 + (n + 1) * 264 + (m + 8) * 2) = l;
            }
        }
    __syncthreads();

    uint32_t* uh = (uint32_t*)g_Uh;
    uint32_t* ul = (uint32_t*)g_Ul;
    const size_t cb = (size_t)b * NFS + nch * 64;
    for (int idx = tid; idx < 4224; idx += 256) {
        int rw = idx >> 5, wq = idx & 31;
        int fc = rw >> 1, il2 = rw & 1;
        uint32_t vh = *(uint32_t*)(SM + fc * 264 + il2 * 128 + wq * 4);
        uint32_t vl = *(uint32_t*)(SM + 17472 + fc * 264 + il2 * 128 + wq * 4);
        size_t di = ((((size_t)fc * CIN + i0 + il2) * MS) + cb) >> 1;
        uh[di + wq] = vh;
        ul[di + wq] = vl;
    }
}

// =====================================================================
// Stage 2: mix (R14, unchanged).
// smem: AH@0(33792) AL@33792 BH@67584(9216) BL@76800; tot 86016
// =====================================================================
#define MIX_SMEM 86016
__global__ __launch_bounds__(256, 2) void k_mix() {
    extern __shared__ __align__(16) char SM[];
    const uint32_t smb = (uint32_t)__cvta_generic_to_shared(SM);
    const int tid = threadIdx.x, w = tid >> 5, lane = tid & 31;
    const int g = lane >> 2, tig = lane & 3;
    const int mat = lane >> 3, row = lane & 7, matb = mat & 1;
    const int fc = blockIdx.y, f = fc >> 1;
    const size_t c0 = (size_t)blockIdx.x * 256;

    {
        const char* uhp = (const char*)g_Uh;
        const char* ulp = (const char*)g_Ul;
        for (int idx = tid; idx < 2048; idx += 256) {
            int i = idx >> 5, ch = idx & 31;
            size_t so = ((((size_t)fc * CIN + i) * MS) + c0) * 2 + ch * 16;
            cpa16(smb + i * 528 + ch * 16, uhp + so);
            cpa16(smb + 33792 + i * 528 + ch * 16, ulp + so);
        }
    }
    {
        const char* whp = (const char*)g_Wh;
        const char* wlp = (const char*)g_Wl;
        for (int idx = tid; idx < 512; idx += 256) {
            int o = idx >> 3, ch = idx & 7;
            size_t so = (((size_t)f * COUT + o) * CIN) * 2 + ch * 16;
            cpa16(smb + 67584 + o * 144 + ch * 16, whp + so);
            cpa16(smb + 76800 + o * 144 + ch * 16, wlp + so);
        }
    }
    cpa_wait();
    __syncthreads();

    const int mb = (w & 3) * 64, nb = (w >> 2) * 32;
    const int krp = (mat >> 1) * 8 + row;
    const uint32_t aB = smb + (uint32_t)(krp * 528);
    const uint32_t bB = smb + 67584u + (uint32_t)((nb + row) * 144 + matb * 16);
    int mcol[4];
#pragma unroll
    for (int mt = 0; mt < 4; mt++) mcol[mt] = (mb + mt * 16 + (mat & 1) * 8) * 2;

    float d[4][4][4];
#pragma unroll
    for (int mt = 0; mt < 4; mt++)
#pragma unroll
        for (int nt = 0; nt < 4; nt++)
#pragma unroll
            for (int q = 0; q < 4; q++) d[mt][nt][q] = 0.f;

#pragma unroll
    for (int kc = 0; kc < 4; kc++) {
        uint32_t bh[4][2], bl[4][2];
#pragma unroll
        for (int nt = 0; nt < 4; nt++) {
            ldsm2(bh[nt], bB + nt * 1152 + kc * 32);
            ldsm2(bl[nt], bB + 9216 + nt * 1152 + kc * 32);
        }
#pragma unroll
        for (int mt = 0; mt < 4; mt++) {
            uint32_t ah[4], al[4];
            ldsm4t(ah, aB + kc * 8448 + mcol[mt]);
            ldsm4t(al, aB + 33792 + kc * 8448 + mcol[mt]);
#pragma unroll
            for (int nt = 0; nt < 4; nt++) {
                mma_bf16(d[mt][nt], ah, bh[nt]);
                mma_bf16(d[mt][nt], al, bh[nt]);
                mma_bf16(d[mt][nt], ah, bl[nt]);
            }
        }
    }
    __syncthreads();   // A dead -> Dt [o][m] pitch 528

#pragma unroll
    for (int mt = 0; mt < 4; mt++)
#pragma unroll
        for (int nt = 0; nt < 4; nt++) {
            int m = mb + mt * 16 + g;
            int oo = nb + nt * 8 + tig * 2;
            uint16_t h, l;
            split2(d[mt][nt][0], h, l);
            *(uint16_t*)(SM + oo * 528 + m * 2) = h;
            *(uint16_t*)(SM + 33792 + oo * 528 + m * 2) = l;
            split2(d[mt][nt][1], h, l);
            *(uint16_t*)(SM + (oo + 1) * 528 + m * 2) = h;
            *(uint16_t*)(SM + 33792 + (oo + 1) * 528 + m * 2) = l;
            split2(d[mt][nt][2], h, l);
            *(uint16_t*)(SM + oo * 528 + (m + 8) * 2) = h;
            *(uint16_t*)(SM + 33792 + oo * 528 + (m + 8) * 2) = l;
            split2(d[mt][nt][3], h, l);
            *(uint16_t*)(SM + (oo + 1) * 528 + (m + 8) * 2) = h;
            *(uint16_t*)(SM + 33792 + (oo + 1) * 528 + (m + 8) * 2) = l;
        }
    __syncthreads();

    uint32_t* yh = (uint32_t*)g_Yh;
    uint32_t* yl = (uint32_t*)g_Yl;
    for (int idx = tid; idx < 8192; idx += 256) {
        int o = idx >> 7, q = idx & 127;
        size_t di = ((((size_t)fc * COUT + o) * MS) + c0) / 2 + q;
        yh[di] = *(uint32_t*)(SM + o * 528 + q * 4);
        yl[di] = *(uint32_t*)(SM + 33792 + o * 528 + q * 4);
    }
}

// =====================================================================
// Stage 3+4: ISTFT frames + OLA.  M=128 (R14 shape) + float2 restage +
// division-free OLA.
// A: Ys[fc(80)][c(128)] pitch 272; B: ID[t'][fc] pitch 176.
// smem: AH@0(21760) AL@21760 IDH@43520(11264) IDL@54784; tot 66048
// =====================================================================
#define FRAMES_SMEM 66048
__global__ __launch_bounds__(256) void k_frames_ola(float* __restrict__ out) {
    extern __shared__ __align__(16) char SM[];
    __shared__ float yc[FC];
    __shared__ float inv[32];
    const uint32_t smb = (uint32_t)__cvta_generic_to_shared(SM);
    const int tid = threadIdx.x, w = tid >> 5, lane = tid & 31;
    const int g = lane >> 2, tig = lane & 3;
    const int mat = lane >> 3, row = lane & 7, matb = mat & 1;
    const int o = blockIdx.y;
    const size_t c0 = (size_t)blockIdx.x * 128;

    {
        const char* yhp = (const char*)g_Yh;
        const char* ylp = (const char*)g_Yl;
        for (int idx = tid; idx < 1056; idx += 256) {
            int fc = idx >> 4, ch = idx & 15;
            size_t so = ((((size_t)fc * COUT + o) * MS) + c0) * 2 + ch * 16;
            cpa16(smb + fc * 272 + ch * 16, yhp + so);
            cpa16(smb + 21760 + fc * 272 + ch * 16, ylp + so);
        }
    }
    for (int idx = tid; idx < 704; idx += 256) {
        cpa16(smb + 43520 + idx * 16, (const char*)g_IDh + idx * 16);
        cpa16(smb + 54784 + idx * 16, (const char*)g_IDl + idx * 16);
    }
    for (int idx = tid; idx < 896; idx += 256) {
        int r = 66 + (idx >> 6), q = idx & 63;
        *(uint32_t*)(SM + r * 272 + q * 4) = 0;
        *(uint32_t*)(SM + 21760 + r * 272 + q * 4) = 0;
    }
    if (tid < FC) {
        float v = 0.f;
        if (blockIdx.x > 0) {
            size_t ei = ((size_t)tid * COUT + o) * MS + c0 - 1;
            v = __bfloat162float(g_Yh[ei]) + __bfloat162float(g_Yl[ei]);
        }
        yc[tid] = v;
    }
    if (tid < 32) {
        float c = cospif((float)tid / 32.0f);
        float w1 = 0.5f - 0.5f * c, w2 = 0.5f + 0.5f * c;
        inv[tid] = 1.0f / (w1 * w1 + w2 * w2);
    }
    cpa_wait();
    __syncthreads();

    const int mb = (w & 3) * 32, nb = (w >> 2) * 32;
    const int krp = (mat >> 1) * 8 + row;
    const uint32_t aB = smb + (uint32_t)(krp * 272);
    const uint32_t bB = smb + 43520u + (uint32_t)((nb + row) * 176 + matb * 16);
    int mcol[2];
#pragma unroll
    for (int mt = 0; mt < 2; mt++) mcol[mt] = (mb + mt * 16 + (mat & 1) * 8) * 2;

    float d[2][4][4];
#pragma unroll
    for (int mt = 0; mt < 2; mt++)
#pragma unroll
        for (int nt = 0; nt < 4; nt++)
#pragma unroll
            for (int q = 0; q < 4; q++) d[mt][nt][q] = 0.f;

#pragma unroll
    for (int kc = 0; kc < 5; kc++) {
        uint32_t bh[4][2], bl[4][2];
#pragma unroll
        for (int nt = 0; nt < 4; nt++) {
            ldsm2(bh[nt], bB + nt * 1408 + kc * 32);
            ldsm2(bl[nt], bB + 11264 + nt * 1408 + kc * 32);
        }
#pragma unroll
        for (int mt = 0; mt < 2; mt++) {
            uint32_t ah[4], al[4];
            ldsm4t(ah, aB + kc * 4352 + mcol[mt]);
            ldsm4t(al, aB + 21760 + kc * 4352 + mcol[mt]);
#pragma unroll
            for (int nt = 0; nt < 4; nt++) {
                mma_bf16(d[mt][nt], ah, bh[nt]);
                mma_bf16(d[mt][nt], al, bh[nt]);
                mma_bf16(d[mt][nt], ah, bl[nt]);
            }
        }
    }

    // boundary frame (c0-1): taps 32..63
    float fm = 0.f;
    if (tid < 32) {
        int t = 32 + tid;
#pragma unroll 11
        for (int q = 0; q < FC; q++) {
            float idv = __bfloat162float(*(__nv_bfloat16*)(SM + 43520 + t * 176 + q * 2))
                      + __bfloat162float(*(__nv_bfloat16*)(SM + 54784 + t * 176 + q * 2));
            fm += idv * yc[q];
        }
    }
    __syncthreads();   // A dead -> F

    float* F = (float*)SM;   // F[i][t'] rows of 68; F[0] = frame c0-1
#pragma unroll
    for (int mt = 0; mt < 2; mt++)
#pragma unroll
        for (int nt = 0; nt < 4; nt++) {
            int m = mb + mt * 16 + g;
            int t = nb + nt * 8 + tig * 2;
            *(float2*)&F[(1 + m) * 68 + t] = make_float2(d[mt][nt][0], d[mt][nt][1]);
            *(float2*)&F[(9 + m) * 68 + t] = make_float2(d[mt][nt][2], d[mt][nt][3]);
        }
    if (tid < 32) F[32 + tid] = fm;
    __syncthreads();

    // OLA: division-free (at most one wrap since r0+127 < 2*NFS)
    const int b0 = (int)(c0 / NFS);
    const int r0 = (int)(c0 - (size_t)b0 * NFS);
    for (int sidx = tid; sidx < 4096; sidx += 256) {
        int i = sidx >> 5, r = sidx & 31;
        int n = r0 + i, b = b0;
        if (n >= NFS) { n -= NFS; b++; }
        if (n < 1 || n >= NFRAME) continue;
        float v = (F[(i + 1) * 68 + r] + F[i * 68 + r + 32]) * inv[r];
        out[(((size_t)(b * COUT + o)) << 14) + (size_t)(n - 1) * 32 + r] = v;
    }
}

// =====================================================================
extern "C" void kernel_launch(void* const* d_in, const int* in_sizes, int n_in,
                              void* d_out, int out_size) {
    const float* x      = (const float*)d_in[0];
    const float* weight = (const float*)d_in[1];
    float* out          = (float*)d_out;
    (void)in_sizes; (void)n_in; (void)out_size;

    static int init = 0;
    if (!init) {
        cudaFuncSetAttribute(k_stft, cudaFuncAttributeMaxDynamicSharedMemorySize, STFT_SMEM);
        cudaFuncSetAttribute(k_mix, cudaFuncAttributeMaxDynamicSharedMemorySize, MIX_SMEM);
        cudaFuncSetAttribute(k_frames_ola, cudaFuncAttributeMaxDynamicSharedMemorySize, FRAMES_SMEM);
        init = 1;
    }

    k_prep_all<<<560, 256>>>(weight);
    k_stft <<<dim3(9, 32, 8), 256, STFT_SMEM>>>(x);
    k_mix  <<<dim3(MS / 256, FC), 256, MIX_SMEM>>>();
    k_frames_ola<<<dim3(MS / 128, COUT), 256, FRAMES_SMEM>>>(out);
}

// round 17
// speedup vs baseline: 1.1201x; 1.0567x over previous
#include <cuda_runtime.h>
#include <cuda_bf16.h>
#include <stdint.h>

// ---------------- problem constants ----------------
#define NFREQ  33
#define FC     66
#define FCP    80
#define BATCH  8
#define CIN    64
#define COUT   64
#define TLEN   16384
#define NFRAME 513
#define NFS    576
#define MS     (BATCH*NFS)   // 4608

// ---------------- global scratch (16B-aligned: cp.async sources) -------------
__device__ __align__(256) __nv_bfloat16 g_Uh[(size_t)FC * CIN  * MS];
__device__ __align__(256) __nv_bfloat16 g_Ul[(size_t)FC * CIN  * MS];
__device__ __align__(256) __nv_bfloat16 g_Yh[(size_t)FC * COUT * MS];
__device__ __align__(256) __nv_bfloat16 g_Yl[(size_t)FC * COUT * MS];
__device__ __align__(256) __nv_bfloat16 g_Wh[(size_t)NFREQ * COUT * CIN];
__device__ __align__(256) __nv_bfloat16 g_Wl[(size_t)NFREQ * COUT * CIN];
__device__ __align__(256) __nv_bfloat16 g_Bth[FCP * 72], g_Btl[FCP * 72];  // [fc][t], pitch 144B
__device__ __align__(256) __nv_bfloat16 g_IDh[64 * 88],  g_IDl[64 * 88];   // [t'][fc], pitch 176B

__device__ __forceinline__ void mma_bf16(float* d, const uint32_t* a, const uint32_t* b) {
    asm volatile(
        "mma.sync.aligned.m16n8k16.row.col.f32.bf16.bf16.f32 "
        "{%0,%1,%2,%3}, {%4,%5,%6,%7}, {%8,%9}, {%0,%1,%2,%3};"
        : "+f"(d[0]), "+f"(d[1]), "+f"(d[2]), "+f"(d[3])
        : "r"(a[0]), "r"(a[1]), "r"(a[2]), "r"(a[3]), "r"(b[0]), "r"(b[1]));
}
__device__ __forceinline__ void ldsm4(uint32_t* r, uint32_t a) {
    asm volatile("ldmatrix.sync.aligned.m8n8.x4.shared.b16 {%0,%1,%2,%3}, [%4];"
        : "=r"(r[0]), "=r"(r[1]), "=r"(r[2]), "=r"(r[3]) : "r"(a));
}
__device__ __forceinline__ void ldsm4t(uint32_t* r, uint32_t a) {
    asm volatile("ldmatrix.sync.aligned.m8n8.x4.trans.shared.b16 {%0,%1,%2,%3}, [%4];"
        : "=r"(r[0]), "=r"(r[1]), "=r"(r[2]), "=r"(r[3]) : "r"(a));
}
__device__ __forceinline__ void ldsm2(uint32_t* r, uint32_t a) {
    asm volatile("ldmatrix.sync.aligned.m8n8.x2.shared.b16 {%0,%1}, [%2];"
        : "=r"(r[0]), "=r"(r[1]) : "r"(a));
}
__device__ __forceinline__ void cpa16(uint32_t smem_dst, const void* gsrc) {
    asm volatile("cp.async.ca.shared.global [%0], [%1], 16;"
        :: "r"(smem_dst), "l"(gsrc));
}
__device__ __forceinline__ void cpa_wait() {
    asm volatile("cp.async.commit_group;\n\tcp.async.wait_group 0;" ::: "memory");
}
__device__ __forceinline__ void split2(float v, uint16_t& h, uint16_t& l) {
    __nv_bfloat16 hb = __float2bfloat16(v);
    __nv_bfloat16 lb = __float2bfloat16(v - __bfloat162float(hb));
    h = *(uint16_t*)&hb; l = *(uint16_t*)&lb;
}

// =====================================================================
// fused table + weight precompute (one launch)
// =====================================================================
__global__ __launch_bounds__(256) void k_prep_all(const float* __restrict__ weight) {
    if (blockIdx.x < 528) {
        int gid = blockIdx.x * 256 + threadIdx.x;
        if (gid >= NFREQ * COUT * CIN) return;
        int f = gid / (COUT * CIN);
        int rem = gid - f * (COUT * CIN);
        int o = rem >> 6, i = rem & 63;
        float w = weight[((size_t)o * CIN + i) * NFREQ + f];
        uint16_t h, l; split2(w, h, l);
        size_t dst = ((size_t)f * COUT + o) * CIN + i;
        ((uint16_t*)g_Wh)[dst] = h; ((uint16_t*)g_Wl)[dst] = l;
        return;
    }
    int tid0 = (blockIdx.x - 528) * 256 + threadIdx.x;
    for (int idx = tid0; idx < FCP * 72; idx += 32 * 256) {
        int fc = idx / 72, t = idx - fc * 72;
        float v = 0.f;
        if (fc < FC && t < 64) {
            int f = fc >> 1;
            float s, c;
            sincospif((float)(f * t) / 32.0f, &s, &c);
            v = (fc & 1) ? -s : c;
            v *= 0.5f - 0.5f * cospif((float)t / 32.0f);
        }
        uint16_t h, l; split2(v, h, l);
        ((uint16_t*)g_Bth)[idx] = h; ((uint16_t*)g_Btl)[idx] = l;
    }
    for (int idx = tid0; idx < 64 * 88; idx += 32 * 256) {
        int t = idx / 88, fc = idx - t * 88;
        float v = 0.f;
        if (fc < FC) {
            int f = fc >> 1;
            float s, c;
            sincospif((float)(f * t) / 32.0f, &s, &c);
            float af = (f == 0 || f == 32) ? 1.0f : 2.0f;
            if (fc & 1) v = (f == 0 || f == 32) ? 0.f : -s * af;
            else        v = c * af;
            v *= (0.5f - 0.5f * cospif((float)t / 32.0f)) * (1.0f / 64.0f);
        }
        uint16_t h, l; split2(v, h, l);
        ((uint16_t*)g_IDh)[idx] = h; ((uint16_t*)g_IDl)[idx] = l;
    }
}

// =====================================================================
// Stage 1: STFT, M=256 (4 channels/block).  D[m=c(256)][n=fc(80)], K=t(64).
// Raw samples staged once per channel: 32-sample groups at pitch 80;
// ldmatrix lane addressing synthesizes the hop-32 frame matrix.
// smem: AH@0 (4ch x 66grp x 80 = 21120) AL@21120
//       BH@42240(11520) BL@53760; stage tot 65280
// Dt alias: DtH@0 (66 x 520 = 34320), DtL@34320; tot 68640
// =====================================================================
#define STFT_SMEM 68640
#define CHB 5280
__global__ __launch_bounds__(256) void k_stft(const float* __restrict__ x) {
    extern __shared__ __align__(16) char SM[];
    const uint32_t smb = (uint32_t)__cvta_generic_to_shared(SM);
    const int tid = threadIdx.x, w = tid >> 5, lane = tid & 31;
    const int g = lane >> 2, tig = lane & 3;
    const int mat = lane >> 3, row = lane & 7, matb = mat & 1;
    const int nch = blockIdx.x, i0 = blockIdx.y * 4, b = blockIdx.z;

    // B tables via cp.async (flat copy, pitch 144)
    for (int idx = tid; idx < 720; idx += 256) {
        cpa16(smb + 42240 + idx * 16, (const char*)g_Bth + idx * 16);
        cpa16(smb + 53760 + idx * 16, (const char*)g_Btl + idx * 16);
    }

    // stage raw samples: 4 channels x 2112 samples
    const float* xr = x + ((size_t)(b * CIN + i0)) * TLEN;
    for (int idx = tid; idx < 8448; idx += 256) {
        int il = idx / 2112;
        int s = idx - il * 2112;
        int src = nch * 2048 + s - 32;
        src = src < 0 ? -src : src;
        src = src >= TLEN ? 2 * TLEN - 2 - src : src;
        float v = xr[(size_t)il * TLEN + src];
        uint16_t h, l; split2(v, h, l);
        int off = il * CHB + (s >> 5) * 80 + (s & 31) * 2;
        *(uint16_t*)(SM + off) = h;
        *(uint16_t*)(SM + 21120 + off) = l;
    }
    cpa_wait();
    __syncthreads();

    const int mb = (w & 3) * 64, nb = (w >> 2) * 40;
    const int il = w & 3;                   // channel of this warp's 64 rows
    const int f_base = (mat & 1) * 8 + row; // frame within 16-row group
    const int t0l = (mat >> 1) * 8;
    uint32_t aK[4];   // r adds 16 frames = +1280
#pragma unroll
    for (int kc = 0; kc < 4; kc++) {
        int tt = t0l + kc * 16;
        aK[kc] = smb + (uint32_t)(il * CHB + (f_base + (tt >> 5)) * 80 + (tt & 31) * 2);
    }
    const uint32_t bB = smb + 42240u + (uint32_t)((nb + row) * 144 + matb * 16);

    float d[4][5][4];
#pragma unroll
    for (int r = 0; r < 4; r++)
#pragma unroll
        for (int nt = 0; nt < 5; nt++)
#pragma unroll
            for (int q = 0; q < 4; q++) d[r][nt][q] = 0.f;

#pragma unroll
    for (int kc = 0; kc < 4; kc++) {
        uint32_t bh[5][2], bl[5][2];
#pragma unroll
        for (int nt = 0; nt < 5; nt++) {
            ldsm2(bh[nt], bB + nt * 1152 + kc * 32);
            ldsm2(bl[nt], bB + 11520 + nt * 1152 + kc * 32);
        }
#pragma unroll
        for (int r = 0; r < 4; r++) {
            uint32_t ah[4], al[4];
            ldsm4(ah, aK[kc] + r * 1280);
            ldsm4(al, aK[kc] + 21120 + r * 1280);
#pragma unroll
            for (int nt = 0; nt < 5; nt++) {
                mma_bf16(d[r][nt], ah, bh[nt]);
                mma_bf16(d[r][nt], al, bh[nt]);
                mma_bf16(d[r][nt], ah, bl[nt]);
            }
        }
    }
    __syncthreads();   // stage area dead -> Dt (pitch 520; DtL@34320)

#pragma unroll
    for (int r = 0; r < 4; r++)
#pragma unroll
        for (int nt = 0; nt < 5; nt++) {
            int m = mb + r * 16 + g;
            int n = nb + nt * 8 + tig * 2;
            uint16_t h, l;
            if (n < FC) {
                split2(d[r][nt][0], h, l);
                *(uint16_t*)(SM + n * 520 + m * 2) = h;
                *(uint16_t*)(SM + 34320 + n * 520 + m * 2) = l;
                split2(d[r][nt][2], h, l);
                *(uint16_t*)(SM + n * 520 + (m + 8) * 2) = h;
                *(uint16_t*)(SM + 34320 + n * 520 + (m + 8) * 2) = l;
            }
            if (n + 1 < FC) {
                split2(d[r][nt][1], h, l);
                *(uint16_t*)(SM + (n + 1) * 520 + m * 2) = h;
                *(uint16_t*)(SM + 34320 + (n + 1) * 520 + m * 2) = l;
                split2(d[r][nt][3], h, l);
                *(uint16_t*)(SM + (n + 1) * 520 + (m + 8) * 2) = h;
                *(uint16_t*)(SM + 34320 + (n + 1) * 520 + (m + 8) * 2) = l;
            }
        }
    __syncthreads();

    uint32_t* uh = (uint32_t*)g_Uh;
    uint32_t* ul = (uint32_t*)g_Ul;
    const size_t cb = (size_t)b * NFS + nch * 64;
    for (int idx = tid; idx < 8448; idx += 256) {
        int rw = idx >> 5, wq = idx & 31;
        int fc = rw >> 2, il2 = rw & 3;
        uint32_t vh = *(uint32_t*)(SM + fc * 520 + il2 * 128 + wq * 4);
        uint32_t vl = *(uint32_t*)(SM + 34320 + fc * 520 + il2 * 128 + wq * 4);
        size_t di = ((((size_t)fc * CIN + i0 + il2) * MS) + cb) >> 1;
        uh[di + wq] = vh;
        ul[di + wq] = vl;
    }
}

// =====================================================================
// Stage 2: mix (unchanged).
// smem: AH@0(33792) AL@33792 BH@67584(9216) BL@76800; tot 86016
// =====================================================================
#define MIX_SMEM 86016
__global__ __launch_bounds__(256, 2) void k_mix() {
    extern __shared__ __align__(16) char SM[];
    const uint32_t smb = (uint32_t)__cvta_generic_to_shared(SM);
    const int tid = threadIdx.x, w = tid >> 5, lane = tid & 31;
    const int g = lane >> 2, tig = lane & 3;
    const int mat = lane >> 3, row = lane & 7, matb = mat & 1;
    const int fc = blockIdx.y, f = fc >> 1;
    const size_t c0 = (size_t)blockIdx.x * 256;

    {
        const char* uhp = (const char*)g_Uh;
        const char* ulp = (const char*)g_Ul;
        for (int idx = tid; idx < 2048; idx += 256) {
            int i = idx >> 5, ch = idx & 31;
            size_t so = ((((size_t)fc * CIN + i) * MS) + c0) * 2 + ch * 16;
            cpa16(smb + i * 528 + ch * 16, uhp + so);
            cpa16(smb + 33792 + i * 528 + ch * 16, ulp + so);
        }
    }
    {
        const char* whp = (const char*)g_Wh;
        const char* wlp = (const char*)g_Wl;
        for (int idx = tid; idx < 512; idx += 256) {
            int o = idx >> 3, ch = idx & 7;
            size_t so = (((size_t)f * COUT + o) * CIN) * 2 + ch * 16;
            cpa16(smb + 67584 + o * 144 + ch * 16, whp + so);
            cpa16(smb + 76800 + o * 144 + ch * 16, wlp + so);
        }
    }
    cpa_wait();
    __syncthreads();

    const int mb = (w & 3) * 64, nb = (w >> 2) * 32;
    const int krp = (mat >> 1) * 8 + row;
    const uint32_t aB = smb + (uint32_t)(krp * 528);
    const uint32_t bB = smb + 67584u + (uint32_t)((nb + row) * 144 + matb * 16);
    int mcol[4];
#pragma unroll
    for (int mt = 0; mt < 4; mt++) mcol[mt] = (mb + mt * 16 + (mat & 1) * 8) * 2;

    float d[4][4][4];
#pragma unroll
    for (int mt = 0; mt < 4; mt++)
#pragma unroll
        for (int nt = 0; nt < 4; nt++)
#pragma unroll
            for (int q = 0; q < 4; q++) d[mt][nt][q] = 0.f;

#pragma unroll
    for (int kc = 0; kc < 4; kc++) {
        uint32_t bh[4][2], bl[4][2];
#pragma unroll
        for (int nt = 0; nt < 4; nt++) {
            ldsm2(bh[nt], bB + nt * 1152 + kc * 32);
            ldsm2(bl[nt], bB + 9216 + nt * 1152 + kc * 32);
        }
#pragma unroll
        for (int mt = 0; mt < 4; mt++) {
            uint32_t ah[4], al[4];
            ldsm4t(ah, aB + kc * 8448 + mcol[mt]);
            ldsm4t(al, aB + 33792 + kc * 8448 + mcol[mt]);
#pragma unroll
            for (int nt = 0; nt < 4; nt++) {
                mma_bf16(d[mt][nt], ah, bh[nt]);
                mma_bf16(d[mt][nt], al, bh[nt]);
                mma_bf16(d[mt][nt], ah, bl[nt]);
            }
        }
    }
    __syncthreads();   // A dead -> Dt [o][m] pitch 528

#pragma unroll
    for (int mt = 0; mt < 4; mt++)
#pragma unroll
        for (int nt = 0; nt < 4; nt++) {
            int m = mb + mt * 16 + g;
            int oo = nb + nt * 8 + tig * 2;
            uint16_t h, l;
            split2(d[mt][nt][0], h, l);
            *(uint16_t*)(SM + oo * 528 + m * 2) = h;
            *(uint16_t*)(SM + 33792 + oo * 528 + m * 2) = l;
            split2(d[mt][nt][1], h, l);
            *(uint16_t*)(SM + (oo + 1) * 528 + m * 2) = h;
            *(uint16_t*)(SM + 33792 + (oo + 1) * 528 + m * 2) = l;
            split2(d[mt][nt][2], h, l);
            *(uint16_t*)(SM + oo * 528 + (m + 8) * 2) = h;
            *(uint16_t*)(SM + 33792 + oo * 528 + (m + 8) * 2) = l;
            split2(d[mt][nt][3], h, l);
            *(uint16_t*)(SM + (oo + 1) * 528 + (m + 8) * 2) = h;
            *(uint16_t*)(SM + 33792 + (oo + 1) * 528 + (m + 8) * 2) = l;
        }
    __syncthreads();

    uint32_t* yh = (uint32_t*)g_Yh;
    uint32_t* yl = (uint32_t*)g_Yl;
    for (int idx = tid; idx < 8192; idx += 256) {
        int o = idx >> 7, q = idx & 127;
        size_t di = ((((size_t)fc * COUT + o) * MS) + c0) / 2 + q;
        yh[di] = *(uint32_t*)(SM + o * 528 + q * 4);
        yl[di] = *(uint32_t*)(SM + 33792 + o * 528 + q * 4);
    }
}

// =====================================================================
// Stage 3+4: ISTFT frames + OLA (R16, unchanged).
// smem: AH@0(21760) AL@21760 IDH@43520(11264) IDL@54784; tot 66048
// =====================================================================
#define FRAMES_SMEM 66048
__global__ __launch_bounds__(256) void k_frames_ola(float* __restrict__ out) {
    extern __shared__ __align__(16) char SM[];
    __shared__ float yc[FC];
    __shared__ float inv[32];
    const uint32_t smb = (uint32_t)__cvta_generic_to_shared(SM);
    const int tid = threadIdx.x, w = tid >> 5, lane = tid & 31;
    const int g = lane >> 2, tig = lane & 3;
    const int mat = lane >> 3, row = lane & 7, matb = mat & 1;
    const int o = blockIdx.y;
    const size_t c0 = (size_t)blockIdx.x * 128;

    {
        const char* yhp = (const char*)g_Yh;
        const char* ylp = (const char*)g_Yl;
        for (int idx = tid; idx < 1056; idx += 256) {
            int fc = idx >> 4, ch = idx & 15;
            size_t so = ((((size_t)fc * COUT + o) * MS) + c0) * 2 + ch * 16;
            cpa16(smb + fc * 272 + ch * 16, yhp + so);
            cpa16(smb + 21760 + fc * 272 + ch * 16, ylp + so);
        }
    }
    for (int idx = tid; idx < 704; idx += 256) {
        cpa16(smb + 43520 + idx * 16, (const char*)g_IDh + idx * 16);
        cpa16(smb + 54784 + idx * 16, (const char*)g_IDl + idx * 16);
    }
    for (int idx = tid; idx < 896; idx += 256) {
        int r = 66 + (idx >> 6), q = idx & 63;
        *(uint32_t*)(SM + r * 272 + q * 4) = 0;
        *(uint32_t*)(SM + 21760 + r * 272 + q * 4) = 0;
    }
    if (tid < FC) {
        float v = 0.f;
        if (blockIdx.x > 0) {
            size_t ei = ((size_t)tid * COUT + o) * MS + c0 - 1;
            v = __bfloat162float(g_Yh[ei]) + __bfloat162float(g_Yl[ei]);
        }
        yc[tid] = v;
    }
    if (tid < 32) {
        float c = cospif((float)tid / 32.0f);
        float w1 = 0.5f - 0.5f * c, w2 = 0.5f + 0.5f * c;
        inv[tid] = 1.0f / (w1 * w1 + w2 * w2);
    }
    cpa_wait();
    __syncthreads();

    const int mb = (w & 3) * 32, nb = (w >> 2) * 32;
    const int krp = (mat >> 1) * 8 + row;
    const uint32_t aB = smb + (uint32_t)(krp * 272);
    const uint32_t bB = smb + 43520u + (uint32_t)((nb + row) * 176 + matb * 16);
    int mcol[2];
#pragma unroll
    for (int mt = 0; mt < 2; mt++) mcol[mt] = (mb + mt * 16 + (mat & 1) * 8) * 2;

    float d[2][4][4];
#pragma unroll
    for (int mt = 0; mt < 2; mt++)
#pragma unroll
        for (int nt = 0; nt < 4; nt++)
#pragma unroll
            for (int q = 0; q < 4; q++) d[mt][nt][q] = 0.f;

#pragma unroll
    for (int kc = 0; kc < 5; kc++) {
        uint32_t bh[4][2], bl[4][2];
#pragma unroll
        for (int nt = 0; nt < 4; nt++) {
            ldsm2(bh[nt], bB + nt * 1408 + kc * 32);
            ldsm2(bl[nt], bB + 11264 + nt * 1408 + kc * 32);
        }
#pragma unroll
        for (int mt = 0; mt < 2; mt++) {
            uint32_t ah[4], al[4];
            ldsm4t(ah, aB + kc * 4352 + mcol[mt]);
            ldsm4t(al, aB + 21760 + kc * 4352 + mcol[mt]);
#pragma unroll
            for (int nt = 0; nt < 4; nt++) {
                mma_bf16(d[mt][nt], ah, bh[nt]);
                mma_bf16(d[mt][nt], al, bh[nt]);
                mma_bf16(d[mt][nt], ah, bl[nt]);
            }
        }
    }

    float fm = 0.f;
    if (tid < 32) {
        int t = 32 + tid;
#pragma unroll 11
        for (int q = 0; q < FC; q++) {
            float idv = __bfloat162float(*(__nv_bfloat16*)(SM + 43520 + t * 176 + q * 2))
                      + __bfloat162float(*(__nv_bfloat16*)(SM + 54784 + t * 176 + q * 2));
            fm += idv * yc[q];
        }
    }
    __syncthreads();   // A dead -> F

    float* F = (float*)SM;
#pragma unroll
    for (int mt = 0; mt < 2; mt++)
#pragma unroll
        for (int nt = 0; nt < 4; nt++) {
            int m = mb + mt * 16 + g;
            int t = nb + nt * 8 + tig * 2;
            *(float2*)&F[(1 + m) * 68 + t] = make_float2(d[mt][nt][0], d[mt][nt][1]);
            *(float2*)&F[(9 + m) * 68 + t] = make_float2(d[mt][nt][2], d[mt][nt][3]);
        }
    if (tid < 32) F[32 + tid] = fm;
    __syncthreads();

    const int b0 = (int)(c0 / NFS);
    const int r0 = (int)(c0 - (size_t)b0 * NFS);
    for (int sidx = tid; sidx < 4096; sidx += 256) {
        int i = sidx >> 5, r = sidx & 31;
        int n = r0 + i, b = b0;
        if (n >= NFS) { n -= NFS; b++; }
        if (n < 1 || n >= NFRAME) continue;
        float v = (F[(i + 1) * 68 + r] + F[i * 68 + r + 32]) * inv[r];
        out[(((size_t)(b * COUT + o)) << 14) + (size_t)(n - 1) * 32 + r] = v;
    }
}

// =====================================================================
extern "C" void kernel_launch(void* const* d_in, const int* in_sizes, int n_in,
                              void* d_out, int out_size) {
    const float* x      = (const float*)d_in[0];
    const float* weight = (const float*)d_in[1];
    float* out          = (float*)d_out;
    (void)in_sizes; (void)n_in; (void)out_size;

    static int init = 0;
    if (!init) {
        cudaFuncSetAttribute(k_stft, cudaFuncAttributeMaxDynamicSharedMemorySize, STFT_SMEM);
        cudaFuncSetAttribute(k_mix, cudaFuncAttributeMaxDynamicSharedMemorySize, MIX_SMEM);
        cudaFuncSetAttribute(k_frames_ola, cudaFuncAttributeMaxDynamicSharedMemorySize, FRAMES_SMEM);
        init = 1;
    }

    k_prep_all<<<560, 256>>>(weight);
    k_stft <<<dim3(9, 16, 8), 256, STFT_SMEM>>>(x);
    k_mix  <<<dim3(MS / 256, FC), 256, MIX_SMEM>>>();
    k_frames_ola<<<dim3(MS / 128, COUT), 256, FRAMES_SMEM>>>(out);
}